// round 15
// baseline (speedup 1.0000x reference)
#include <cuda_runtime.h>
#include <cstdint>

// Problem constants
#define S   8192
#define Dm  2048
#define E   64
#define CAP 128   // ceil(S/E * 1.0)

#define GATE_BLOCKS (S / 64)   // 128 blocks, one per SM; chunk == block == 64 tokens

// ---------------- device scratch (no allocations allowed) ----------------
__device__ int   g_expert[S];
__device__ float g_gate[S];
__device__ int   g_rank[S];                      // rank within 64-token chunk
__device__ int   g_chunkHist[GATE_BLOCKS * 64];  // [chunk][expert]
__device__ float g_partSum[GATE_BLOCKS * 64];    // per-block gate column sums

// ---------------------------------------------------------------------------
// Kernel 1: logits = x @ wg^T (R12 double-buffered mainloop, unchanged), then
// softmax/argmax/gate, per-block column sums, fused per-chunk histogram +
// within-chunk ranks. BYTE-IDENTICAL math to R14.
// ---------------------------------------------------------------------------
__global__ __launch_bounds__(256, 1) void gate_kernel(const float* __restrict__ x,
                                                      const float* __restrict__ wg) {
    __shared__ __align__(16) float xs[2][16][68];  // [buf][k][token]
    __shared__ __align__(16) float ws[2][16][68];  // [buf][k][expert]
    __shared__ float colv[16][64];
    __shared__ int   sexp[64];
    __shared__ int   whist[2][64];

    const int tid = threadIdx.x;
    const int ty  = tid >> 4;      // 0..15 -> token quad
    const int tx  = tid & 15;      // 0..15 -> expert quad
    const int sb  = blockIdx.x * 64;

    float acc[4][4];
#pragma unroll
    for (int i = 0; i < 4; i++)
#pragma unroll
        for (int j = 0; j < 4; j++) acc[i][j] = 0.0f;

    const int row = tid >> 2;          // token / expert 0..63
    const int kq  = (tid & 3) * 4;     // k offset (float4)

    const float* xrow = x  + (size_t)(sb + row) * Dm + kq;
    const float* wrow = wg + (size_t)row * Dm + kq;

    const int NT = Dm / 16;  // 128 k-tiles

    // prologue: tile 0 into buf0, prefetch tile 1 into regs
    float4 xv = *(const float4*)(xrow);
    float4 wv = *(const float4*)(wrow);
    xs[0][kq    ][row] = xv.x;  xs[0][kq + 1][row] = xv.y;
    xs[0][kq + 2][row] = xv.z;  xs[0][kq + 3][row] = xv.w;
    ws[0][kq    ][row] = wv.x;  ws[0][kq + 1][row] = wv.y;
    ws[0][kq + 2][row] = wv.z;  ws[0][kq + 3][row] = wv.w;
    xv = *(const float4*)(xrow + 16);
    wv = *(const float4*)(wrow + 16);
    __syncthreads();

    for (int t = 0; t < NT; t++) {
        const int cb = t & 1;        // compute buffer
        const int sbuf = cb ^ 1;     // store buffer (tile t+1)

        if (t + 1 < NT) {            // store prefetched tile t+1
            xs[sbuf][kq    ][row] = xv.x;  xs[sbuf][kq + 1][row] = xv.y;
            xs[sbuf][kq + 2][row] = xv.z;  xs[sbuf][kq + 3][row] = xv.w;
            ws[sbuf][kq    ][row] = wv.x;  ws[sbuf][kq + 1][row] = wv.y;
            ws[sbuf][kq + 2][row] = wv.z;  ws[sbuf][kq + 3][row] = wv.w;
        }
        if (t + 2 < NT) {            // prefetch tile t+2
            xv = *(const float4*)(xrow + (t + 2) * 16);
            wv = *(const float4*)(wrow + (t + 2) * 16);
        }

#pragma unroll
        for (int kk = 0; kk < 16; kk++) {
            const float4 a = *(const float4*)&xs[cb][kk][ty * 4];
            const float4 b = *(const float4*)&ws[cb][kk][tx * 4];
            acc[0][0] += a.x * b.x;  acc[0][1] += a.x * b.y;
            acc[0][2] += a.x * b.z;  acc[0][3] += a.x * b.w;
            acc[1][0] += a.y * b.x;  acc[1][1] += a.y * b.y;
            acc[1][2] += a.y * b.z;  acc[1][3] += a.y * b.w;
            acc[2][0] += a.z * b.x;  acc[2][1] += a.z * b.y;
            acc[2][2] += a.z * b.z;  acc[2][3] += a.z * b.w;
            acc[3][0] += a.w * b.x;  acc[3][1] += a.w * b.y;
            acc[3][2] += a.w * b.z;  acc[3][3] += a.w * b.w;
        }
        __syncthreads();   // single barrier per tile
    }

    // softmax + argmax per token (16 lanes per token group; width-16 shuffles)
    const unsigned FULL = 0xffffffffu;
    float cadd[4] = {0.0f, 0.0f, 0.0f, 0.0f};

#pragma unroll
    for (int i = 0; i < 4; i++) {
        float m = fmaxf(fmaxf(acc[i][0], acc[i][1]), fmaxf(acc[i][2], acc[i][3]));
#pragma unroll
        for (int d = 8; d >= 1; d >>= 1)
            m = fmaxf(m, __shfl_xor_sync(FULL, m, d, 16));

        float ev0 = __expf(acc[i][0] - m);
        float ev1 = __expf(acc[i][1] - m);
        float ev2 = __expf(acc[i][2] - m);
        float ev3 = __expf(acc[i][3] - m);
        float ssum = ev0 + ev1 + ev2 + ev3;
#pragma unroll
        for (int d = 8; d >= 1; d >>= 1)
            ssum += __shfl_xor_sync(FULL, ssum, d, 16);
        const float rs = 1.0f / ssum;

        cadd[0] += ev0 * rs;  cadd[1] += ev1 * rs;
        cadd[2] += ev2 * rs;  cadd[3] += ev3 * rs;

        // argmax (first occurrence on ties)
        float bv = acc[i][0]; int bidx = tx * 4;
#pragma unroll
        for (int j = 1; j < 4; j++)
            if (acc[i][j] > bv) { bv = acc[i][j]; bidx = tx * 4 + j; }
#pragma unroll
        for (int d = 8; d >= 1; d >>= 1) {
            float ov = __shfl_xor_sync(FULL, bv, d, 16);
            int   oi = __shfl_xor_sync(FULL, bidx, d, 16);
            if (ov > bv || (ov == bv && oi < bidx)) { bv = ov; bidx = oi; }
        }
        if (tx == 0) {
            const int s = sb + ty * 4 + i;
            g_expert[s] = bidx;
            g_gate[s]   = rs;
            sexp[ty * 4 + i] = bidx;
        }
    }

    // per-block column sums + fused rank computation
#pragma unroll
    for (int j = 0; j < 4; j++) colv[ty][tx * 4 + j] = cadd[j];
    if (tid < 128) ((int*)whist)[tid] = 0;
    __syncthreads();

    if (tid < 64) {
        float sum = 0.0f;
#pragma unroll
        for (int r = 0; r < 16; r++) sum += colv[r][tid];
        g_partSum[blockIdx.x * 64 + tid] = sum;
    }

    int rnk_e = 0; int rnk_rw = 0;
    if (tid < 64) {   // warps 0,1 fully active -> full-mask match_any is valid
        rnk_e = sexp[tid];
        const unsigned mm = __match_any_sync(FULL, rnk_e);
        const int lane = tid & 31;
        rnk_rw = __popc(mm & ((1u << lane) - 1u));
        if ((int)(__ffs(mm) - 1) == lane) whist[tid >> 5][rnk_e] = __popc(mm);
    }
    __syncthreads();
    if (tid < 64) {
        const int before = (tid >= 32) ? whist[0][rnk_e] : 0;
        g_rank[sb + tid] = rnk_rw + before;
        g_chunkHist[blockIdx.x * 64 + tid] = whist[0][tid] + whist[1][tid];
    }
}

// ---------------------------------------------------------------------------
// Kernel 2: fused zero-fill + scatter + (block 0) l_aux. One block per token:
// writes its 8192-float combine row and mask row as zeros with the token's
// value placed in-line. Same 537MB store traffic as the memset, but the
// scatter, scan kernel, and their launch/join overhead disappear.
// ---------------------------------------------------------------------------
__global__ __launch_bounds__(256) void fill_kernel(float* __restrict__ out,
                                                   long combine_base, int has_mask,
                                                   int has_laux) {
    const int s   = blockIdx.x;
    const int tid = threadIdx.x;
    const unsigned FULL = 0xffffffffu;

    __shared__ int   starget;   // row-relative index e*CAP+loc, or -1 (dropped)
    __shared__ float sgate;
    __shared__ int   wsum[4];

    // expert-queue base: exclusive prefix over chunks (threads 0..127 own one chunk each)
    const int e = g_expert[s];
    const int myChunk = s >> 6;
    int h = 0;
    if (tid < 128 && tid < myChunk) h = g_chunkHist[tid * 64 + e];
#pragma unroll
    for (int d = 16; d >= 1; d >>= 1) h += __shfl_xor_sync(FULL, h, d);
    if ((tid & 31) == 0 && tid < 128) wsum[tid >> 5] = h;
    __syncthreads();
    if (tid == 0) {
        const int base = wsum[0] + wsum[1] + wsum[2] + wsum[3];
        const int loc = base + g_rank[s];
        starget = (loc < CAP) ? e * CAP + loc : -1;
        sgate = g_gate[s];
    }
    __syncthreads();

    const int target = starget;
    const float gval = sgate;

#pragma unroll
    for (int r = 0; r < 2; r++) {                       // r=0 combine, r=1 mask
        if (r == 1 && !has_mask) break;
        const float val = (r == 0) ? gval : 1.0f;
        float* p = out + combine_base + (long)s * (E * CAP) + (long)r * S * E * CAP;

        const int head = (int)((16u - ((unsigned)(uintptr_t)p & 15u)) & 15u) >> 2;  // 0..3
        if (tid < head) p[tid] = (tid == target) ? val : 0.0f;

        float4* p4 = (float4*)(p + head);
        const int n4 = (E * CAP - head) >> 2;
        const int tail = E * CAP - head - n4 * 4;
        for (int i = tid; i < n4; i += 256) {
            float4 v = make_float4(0.f, 0.f, 0.f, 0.f);
            const int fi = head + i * 4;
            if ((unsigned)(target - fi) < 4u) ((float*)&v)[target - fi] = val;
            p4[i] = v;
        }
        if (tid < tail) {
            const int fi = head + n4 * 4 + tid;
            p[fi] = (fi == target) ? val : 0.0f;
        }
    }

    // block 0: l_aux, replicating the old scan_kernel's exact reduction order
    if (s == 0 && has_laux && tid < 64) {
        const int e2 = tid;
        int run = 0;
        for (int b = 0; b < GATE_BLOCKS; b++) run += g_chunkHist[b * 64 + e2];
        float gs = 0.0f;
        for (int p = 0; p < GATE_BLOCKS; p++) gs += g_partSum[p * 64 + e2];

        float contrib = gs * (float)run;
#pragma unroll
        for (int d = 16; d >= 1; d >>= 1)
            contrib += __shfl_xor_sync(FULL, contrib, d);

        __shared__ float part[2];
        if ((tid & 31) == 0) part[tid >> 5] = contrib;
        __syncwarp();
        if (tid == 32) part[1] = contrib;   // already set above; keep simple
        __syncthreads();
        if (tid == 0)
            out[0] = ((float)E / ((float)S * (float)S)) * (part[0] + part[1]);
    }
}

// ---------------------------------------------------------------------------
extern "C" void kernel_launch(void* const* d_in, const int* in_sizes, int n_in,
                              void* d_out, int out_size) {
    const float* x  = (const float*)d_in[0];
    const float* wg = (const float*)d_in[1];
    float* out = (float*)d_out;

    const long SEC = (long)S * E * CAP;                 // 67,108,864
    const int has_mask = ((long)out_size >= 2 * SEC);
    const long cb = (long)out_size - (has_mask ? 2 : 1) * SEC;  // 1 if l_aux packed
    const int has_laux = (cb > 0);

    gate_kernel<<<GATE_BLOCKS, 256>>>(x, wg);
    fill_kernel<<<S, 256>>>(out, cb, has_mask, has_laux);
}